// round 9
// baseline (speedup 1.0000x reference)
#include <cuda_runtime.h>
#include <math.h>
#include <float.h>

#define BATCH 2
#define NPTS  4096
#define FDIM  64
#define KNN   20
#define NROWS (BATCH*NPTS)

// Scratch (static __device__ arrays -- no allocation)
__device__ float  g_Wh[NROWS*FDIM];
__device__ float  g_f1[NROWS];
__device__ float  g_f2[NROWS];
__device__ float4 g_pos4[NROWS];

// ---------------------------------------------------------------------------
// Kernel 1: Wh = x@W ; f1 = Wh@a[:64] ; f2 = Wh@a[64:] ; pos4 = (x,y,z,|p|^2)
// W transposed into smem (pad 68) -> float4 LDS for the dot product.
// ---------------------------------------------------------------------------
__global__ void __launch_bounds__(256) prep_kernel(
        const float* __restrict__ x,
        const float* __restrict__ pos,
        const float* __restrict__ W,
        const float* __restrict__ a)
{
    __shared__ float WsT[FDIM*68];     // WsT[f*68 + k2] = W[k2*64 + f]
    __shared__ float xs[4][FDIM];
    __shared__ float red1[8];
    __shared__ float red2[8];

    int tid = threadIdx.x;
    for (int i = tid; i < FDIM*FDIM; i += 256)
        WsT[(i & 63)*68 + (i >> 6)] = W[i];

    int r   = tid >> 6;            // local row 0..3
    int f   = tid & 63;            // feature
    int row = blockIdx.x * 4 + r;  // global row in [0, B*N)
    xs[r][f] = x[row*FDIM + f];
    __syncthreads();

    float acc = 0.f;
    #pragma unroll
    for (int k4 = 0; k4 < 16; k4++) {
        float4 xv = *(const float4*)&xs[r][k4*4];
        float4 wv = *(const float4*)&WsT[f*68 + k4*4];
        acc += xv.x*wv.x; acc += xv.y*wv.y;
        acc += xv.z*wv.z; acc += xv.w*wv.w;
    }
    g_Wh[row*FDIM + f] = acc;

    float c1 = acc * a[f];
    float c2 = acc * a[FDIM + f];
    #pragma unroll
    for (int off = 16; off; off >>= 1) {
        c1 += __shfl_down_sync(0xffffffffu, c1, off);
        c2 += __shfl_down_sync(0xffffffffu, c2, off);
    }
    int warp = tid >> 5;
    if ((tid & 31) == 0) { red1[warp] = c1; red2[warp] = c2; }
    __syncthreads();
    if (f == 0) {
        g_f1[row] = red1[2*r] + red1[2*r + 1];
        g_f2[row] = red2[2*r] + red2[2*r + 1];
    }

    if (tid < 4) {
        int rw = blockIdx.x * 4 + tid;
        float px = pos[rw*3 + 0], py = pos[rw*3 + 1], pz = pos[rw*3 + 2];
        g_pos4[rw] = make_float4(px, py, pz, px*px + py*py + pz*pz);
    }
}

// Order-preserving f32 -> u32 map (min over keys == min over floats)
__device__ __forceinline__ unsigned mono32(float v) {
    unsigned u = __float_as_uint(v);
    return u ^ ((unsigned)((int)u >> 31) | 0x80000000u);
}

// min over 16 keys as (key<<4)|slot, explicit depth-4 tree (no dyn indexing)
__device__ __forceinline__ unsigned long long min16(const unsigned* key32) {
    unsigned long long t[16];
    #pragma unroll
    for (int s = 0; s < 16; s++)
        t[s] = (((unsigned long long)key32[s]) << 4) | (unsigned)s;
    #pragma unroll
    for (int d = 8; d; d >>= 1)
        #pragma unroll
        for (int i = 0; i < 16; i += 16/ (d==8?1:1)) break; // (placeholder, real tree below)
    // explicit tree
    unsigned long long a0 = t[0]  < t[1]  ? t[0]  : t[1];
    unsigned long long a1 = t[2]  < t[3]  ? t[2]  : t[3];
    unsigned long long a2 = t[4]  < t[5]  ? t[4]  : t[5];
    unsigned long long a3 = t[6]  < t[7]  ? t[6]  : t[7];
    unsigned long long a4 = t[8]  < t[9]  ? t[8]  : t[9];
    unsigned long long a5 = t[10] < t[11] ? t[10] : t[11];
    unsigned long long a6 = t[12] < t[13] ? t[12] : t[13];
    unsigned long long a7 = t[14] < t[15] ? t[14] : t[15];
    unsigned long long b0 = a0 < a1 ? a0 : a1;
    unsigned long long b1 = a2 < a3 ? a2 : a3;
    unsigned long long b2 = a4 < a5 ? a4 : a5;
    unsigned long long b3 = a6 < a7 ? a6 : a7;
    unsigned long long c0 = b0 < b1 ? b0 : b1;
    unsigned long long c1 = b2 < b3 ? b2 : b3;
    return c0 < c1 ? c0 : c1;
}

// ---------------------------------------------------------------------------
// Kernel 2: fused KNN(21, drop self) + edge softmax + aggregation + pos MLP
// One 256-thread block per query. Selection is WARP-LOCAL (no barriers):
// each warp extracts its top-21 of its 512 candidates via 2x REDUX per round;
// merge of the 8x21 winners by exact rank-select. 3 block barriers total.
// ---------------------------------------------------------------------------
__global__ void __launch_bounds__(256) gat_kernel(
        const float* __restrict__ Wp,
        const float* __restrict__ bp,
        float* __restrict__ out)
{
    __shared__ unsigned long long mk[8*(KNN+1)];  // per-warp winners, key<<12|m
    __shared__ int   nbr[KNN + 1];                // global winners in rank order
    __shared__ float attn[KNN];

    int tid  = threadIdx.x;
    int lane = tid & 31;
    int warp = tid >> 5;

    int q = blockIdx.x;          // flattened b*N + n
    int b = q >> 12;             // N = 4096
    const float4* posb = g_pos4 + (b << 12);
    float4 qp = g_pos4[q];

    // ---- Phase 1: d2 keys for this warp's 512-candidate chunk ----
    // candidate id: m = warp*512 + s*32 + lane
    unsigned key32[16];
    #pragma unroll
    for (int s = 0; s < 16; s++) {
        float4 p = posb[(warp << 9) + (s << 5) + lane];
        float dot = qp.x*p.x + qp.y*p.y + qp.z*p.z;
        float d2  = (qp.w + p.w) - 2.0f*dot;     // identical to passing kernel
        key32[s] = mono32(d2);
    }
    unsigned long long lk = min16(key32);        // (key<<4)|slot

    // ---- Phase 2: per-warp top-21 extraction, barrier-free ----
    for (int r = 0; r < KNN + 1; r++) {
        unsigned v    = (unsigned)(lk >> 4);
        unsigned winv = __reduce_min_sync(0xffffffffu, v);
        unsigned m_me = (unsigned)((warp << 9) | (((unsigned)lk & 15u) << 5) | lane);
        unsigned am   = (v == winv) ? m_me : 0xffffffffu;
        unsigned winm = __reduce_min_sync(0xffffffffu, am);
        if (am == winm) {                        // unique owner lane
            mk[warp*(KNN+1) + r] =
                (((unsigned long long)winv) << 12) | winm;
            int slot = (int)(lk & 15u);
            #pragma unroll
            for (int s = 0; s < 16; s++) if (s == slot) key32[s] = 0xffffffffu;
            lk = min16(key32);
        }
    }
    __syncthreads();

    // ---- Phase 2b: exact rank-select over the 168 candidate winners ----
    // keys are globally unique ((d2key, m) lexicographic == top_k order)
    if (tid < 8*(KNN+1)) {
        unsigned long long myk = mk[tid];
        int rank = 0;
        #pragma unroll 8
        for (int j = 0; j < 8*(KNN+1); j++)
            rank += (mk[j] < myk);
        if (rank <= KNN) nbr[rank] = (int)(myk & 0xFFFu);
    }
    __syncthreads();

    // ---- Phase 3: edge scores + softmax over the 20 neighbors (warp 0) ----
    if (warp == 0) {
        float e = -FLT_MAX;
        if (lane >= 1 && lane < KNN + 1) {
            int m = nbr[lane];
            e = g_f1[q] + g_f2[(b << 12) + m];
            e = (e > 0.f) ? e : 0.2f * e;        // leaky relu
        }
        float mx = e;
        #pragma unroll
        for (int off = 16; off; off >>= 1)
            mx = fmaxf(mx, __shfl_xor_sync(0xffffffffu, mx, off));
        float p = (lane >= 1 && lane < KNN + 1) ? expf(e - mx) : 0.f;
        float sm = p;
        #pragma unroll
        for (int off = 16; off; off >>= 1)
            sm += __shfl_xor_sync(0xffffffffu, sm, off);
        if (lane >= 1 && lane < KNN + 1) attn[lane - 1] = p / sm;
    }
    __syncthreads();

    // ---- Phase 4: h = attn @ Wh[nbr] + relu(pos@Wp + bp); elu ----
    if (tid < FDIM) {
        const float* whb = g_Wh + ((size_t)(b << 12)) * FDIM;
        float acc = 0.f;
        #pragma unroll
        for (int j = 0; j < KNN; j++)
            acc += attn[j] * whb[nbr[j + 1] * FDIM + tid];
        float pf = qp.x*Wp[tid] + qp.y*Wp[FDIM + tid] + qp.z*Wp[2*FDIM + tid] + bp[tid];
        pf = fmaxf(pf, 0.f);
        float h = acc + pf;
        out[(size_t)q * FDIM + tid] = (h > 0.f) ? h : expm1f(h);
    }
}

// ---------------------------------------------------------------------------
extern "C" void kernel_launch(void* const* d_in, const int* in_sizes, int n_in,
                              void* d_out, int out_size)
{
    const float* x   = (const float*)d_in[0];
    const float* pos = (const float*)d_in[1];
    const float* W   = (const float*)d_in[2];
    const float* a   = (const float*)d_in[3];
    const float* Wp  = (const float*)d_in[4];
    const float* bp  = (const float*)d_in[5];
    // d_in[6] is k (=20), compiled in.

    prep_kernel<<<NROWS / 4, 256>>>(x, pos, W, a);
    gat_kernel<<<NROWS, 256>>>(Wp, bp, (float*)d_out);
}

// round 11
// speedup vs baseline: 1.0362x; 1.0362x over previous
#include <cuda_runtime.h>
#include <math.h>
#include <float.h>

#define BATCH 2
#define NPTS  4096
#define FDIM  64
#define KNN   20
#define NROWS (BATCH*NPTS)
#define NSEL  (KNN + 1)          // 21: top-21, rank 0 (self) dropped

// Scratch (static __device__ arrays -- no allocation)
__device__ float  g_Wh[NROWS*FDIM];
__device__ float  g_f1[NROWS];
__device__ float  g_f2[NROWS];
__device__ float4 g_pos4[NROWS];

// ---------------------------------------------------------------------------
// Kernel 1: Wh = x@W ; f1 = Wh@a[:64] ; f2 = Wh@a[64:] ; pos4 = (x,y,z,|p|^2)
// ---------------------------------------------------------------------------
__global__ void __launch_bounds__(256) prep_kernel(
        const float* __restrict__ x,
        const float* __restrict__ pos,
        const float* __restrict__ W,
        const float* __restrict__ a)
{
    __shared__ float WsT[FDIM*68];     // WsT[f*68 + k2] = W[k2*64 + f]
    __shared__ float xs[4][FDIM];
    __shared__ float red1[8];
    __shared__ float red2[8];

    int tid = threadIdx.x;
    for (int i = tid; i < FDIM*FDIM; i += 256)
        WsT[(i & 63)*68 + (i >> 6)] = W[i];

    int r   = tid >> 6;            // local row 0..3
    int f   = tid & 63;            // feature
    int row = blockIdx.x * 4 + r;  // global row in [0, B*N)
    xs[r][f] = x[row*FDIM + f];
    __syncthreads();

    float acc = 0.f;
    #pragma unroll
    for (int k4 = 0; k4 < 16; k4++) {
        float4 xv = *(const float4*)&xs[r][k4*4];
        float4 wv = *(const float4*)&WsT[f*68 + k4*4];
        acc += xv.x*wv.x; acc += xv.y*wv.y;
        acc += xv.z*wv.z; acc += xv.w*wv.w;
    }
    g_Wh[row*FDIM + f] = acc;

    float c1 = acc * a[f];
    float c2 = acc * a[FDIM + f];
    #pragma unroll
    for (int off = 16; off; off >>= 1) {
        c1 += __shfl_down_sync(0xffffffffu, c1, off);
        c2 += __shfl_down_sync(0xffffffffu, c2, off);
    }
    int warp = tid >> 5;
    if ((tid & 31) == 0) { red1[warp] = c1; red2[warp] = c2; }
    __syncthreads();
    if (f == 0) {
        g_f1[row] = red1[2*r] + red1[2*r + 1];
        g_f2[row] = red2[2*r] + red2[2*r + 1];
    }

    if (tid < 4) {
        int rw = blockIdx.x * 4 + tid;
        float px = pos[rw*3 + 0], py = pos[rw*3 + 1], pz = pos[rw*3 + 2];
        g_pos4[rw] = make_float4(px, py, pz, px*px + py*py + pz*pz);
    }
}

// Order-preserving f32 -> u32 map (min over keys == min over floats)
__device__ __forceinline__ unsigned mono32(float v) {
    unsigned u = __float_as_uint(v);
    return u ^ ((unsigned)((int)u >> 31) | 0x80000000u);
}

// ---------------------------------------------------------------------------
// Kernel 2: fused KNN(21) + edge softmax + aggregation + pos MLP.
// One 256-thread block per query. Selection = exact radix select (4 passes
// of 8 bits) over monotonic u32 keys; boundary ties broken by lowest index
// (= jax.lax.top_k semantics); winners rank-ordered; rank 0 (self) dropped.
// ---------------------------------------------------------------------------
__global__ void __launch_bounds__(256) gat_kernel(
        const float* __restrict__ Wp,
        const float* __restrict__ bp,
        float* __restrict__ out)
{
    __shared__ unsigned hist[256];
    __shared__ unsigned pivot_digit_s, cnt_below_s, target_s;
    __shared__ unsigned sel_cnt, eq_cnt;
    __shared__ unsigned long long sel[NSEL];   // (key<<12)|m, unordered
    __shared__ unsigned eq_m[64];
    __shared__ int   nbr[NSEL];                // rank order
    __shared__ float attn[KNN];

    int tid  = threadIdx.x;
    int lane = tid & 31;
    int warp = tid >> 5;

    int q = blockIdx.x;          // flattened b*N + n
    int b = q >> 12;             // N = 4096
    const float4* posb = g_pos4 + (b << 12);
    float4 qp = g_pos4[q];

    // ---- Phase 1: monotonic d2 keys, 16 per thread (m = s*256 + tid) ----
    unsigned key[16];
    #pragma unroll
    for (int s = 0; s < 16; s++) {
        float4 p = posb[s*256 + tid];
        float dot = qp.x*p.x + qp.y*p.y + qp.z*p.z;
        float d2  = (qp.w + p.w) - 2.0f*dot;     // identical to passing kernels
        key[s] = mono32(d2);
    }

    // ---- Phase 2: radix select the 21 smallest keys ----
    unsigned active = 0xFFFFu;   // slot is still a pivot candidate
    unsigned strict = 0;         // slot is strictly below final threshold
    unsigned K21 = 0;            // assembled threshold key

    if (tid == 0) target_s = NSEL;

    #pragma unroll
    for (int pass = 0; pass < 4; pass++) {
        int shift = 24 - 8*pass;
        hist[tid] = 0;
        __syncthreads();                         // A

        // warp-aggregated histogram of active slots
        #pragma unroll
        for (int s = 0; s < 16; s++) {
            bool act = (active >> s) & 1;
            unsigned d = act ? ((key[s] >> shift) & 255u) : 0xFFFFFFFFu;
            unsigned mm = __match_any_sync(0xffffffffu, d);
            if (act && lane == (__ffs(mm) - 1))
                atomicAdd(&hist[d], (unsigned)__popc(mm));
        }
        __syncthreads();                         // B

        if (warp == 0) {
            unsigned c[8], sum = 0;
            #pragma unroll
            for (int i = 0; i < 8; i++) { c[i] = hist[lane*8 + i]; sum += c[i]; }
            unsigned excl = sum;
            #pragma unroll
            for (int off = 1; off < 32; off <<= 1) {
                unsigned nb = __shfl_up_sync(0xffffffffu, excl, off);
                if (lane >= off) excl += nb;
            }
            excl -= sum;                         // exclusive prefix of lane sums
            unsigned T = target_s;
            unsigned run = excl, below = 0; int found = -1;
            #pragma unroll
            for (int i = 0; i < 8; i++) {
                if (found < 0 && run < T && run + c[i] >= T) { found = i; below = run; }
                run += c[i];
            }
            if (found >= 0) {                    // exactly one lane
                pivot_digit_s = lane*8 + found;
                cnt_below_s   = below;
            }
        }
        __syncthreads();                         // C

        unsigned pd = pivot_digit_s;
        K21 |= pd << shift;
        if (tid == 0) target_s -= cnt_below_s;
        #pragma unroll
        for (int s = 0; s < 16; s++) {
            if ((active >> s) & 1) {
                unsigned d = (key[s] >> shift) & 255u;
                if (d < pd)      { strict |= 1u << s; active &= ~(1u << s); }
                else if (d > pd) {                   active &= ~(1u << s); }
            }
        }
    }

    // ---- Phase 2b: assemble the 21 winners ----
    if (tid == 0) { sel_cnt = 0; eq_cnt = 0; }
    __syncthreads();
    #pragma unroll
    for (int s = 0; s < 16; s++) {
        unsigned m = (unsigned)(s*256 + tid);
        if ((strict >> s) & 1) {
            unsigned i = atomicAdd(&sel_cnt, 1u);
            sel[i] = (((unsigned long long)key[s]) << 12) | m;
        }
        if ((active >> s) & 1) {                 // key == K21
            unsigned e = atomicAdd(&eq_cnt, 1u);
            if (e < 64) eq_m[e] = m;
        }
    }
    __syncthreads();
    if (warp == 0) {                             // take lowest-index ties
        unsigned t    = target_s;                // >= 1
        unsigned base = NSEL - t;
        for (unsigned i = 0; i < t; i++) {
            unsigned ec = min(eq_cnt, 64u);
            unsigned v0 = (lane      < (int)ec) ? eq_m[lane]      : 0xFFFFFFFFu;
            unsigned v1 = (lane + 32 < (int)ec) ? eq_m[lane + 32] : 0xFFFFFFFFu;
            unsigned v  = min(v0, v1);
            unsigned winm = __reduce_min_sync(0xffffffffu, v);
            if (v0 == winm)      eq_m[lane]      = 0xFFFFFFFFu;
            else if (v1 == winm) eq_m[lane + 32] = 0xFFFFFFFFu;
            if (lane == 0)
                sel[base + i] = (((unsigned long long)K21) << 12) | winm;
        }
    }
    __syncthreads();

    // ---- Phase 2c: rank the 21 winners (keys unique) -> reference order ----
    if (tid < NSEL) {
        unsigned long long myk = sel[tid];
        int rank = 0;
        #pragma unroll
        for (int j = 0; j < NSEL; j++) rank += (sel[j] < myk);
        nbr[rank] = (int)(myk & 0xFFFu);
    }
    __syncthreads();

    // ---- Phase 3: edge scores + softmax over the 20 neighbors (warp 0) ----
    if (warp == 0) {
        float e = -FLT_MAX;
        if (lane >= 1 && lane < NSEL) {
            int m = nbr[lane];
            e = g_f1[q] + g_f2[(b << 12) + m];
            e = (e > 0.f) ? e : 0.2f * e;        // leaky relu
        }
        float mx = e;
        #pragma unroll
        for (int off = 16; off; off >>= 1)
            mx = fmaxf(mx, __shfl_xor_sync(0xffffffffu, mx, off));
        float p = (lane >= 1 && lane < NSEL) ? expf(e - mx) : 0.f;
        float sm = p;
        #pragma unroll
        for (int off = 16; off; off >>= 1)
            sm += __shfl_xor_sync(0xffffffffu, sm, off);
        if (lane >= 1 && lane < NSEL) attn[lane - 1] = p / sm;
    }
    __syncthreads();

    // ---- Phase 4: h = attn @ Wh[nbr] + relu(pos@Wp + bp); elu ----
    if (tid < FDIM) {
        const float* whb = g_Wh + ((size_t)(b << 12)) * FDIM;
        float acc = 0.f;
        #pragma unroll
        for (int j = 0; j < KNN; j++)
            acc += attn[j] * whb[nbr[j + 1] * FDIM + tid];
        float pf = qp.x*Wp[tid] + qp.y*Wp[FDIM + tid] + qp.z*Wp[2*FDIM + tid] + bp[tid];
        pf = fmaxf(pf, 0.f);
        float h = acc + pf;
        out[(size_t)q * FDIM + tid] = (h > 0.f) ? h : expm1f(h);
    }
}

// ---------------------------------------------------------------------------
extern "C" void kernel_launch(void* const* d_in, const int* in_sizes, int n_in,
                              void* d_out, int out_size)
{
    const float* x   = (const float*)d_in[0];
    const float* pos = (const float*)d_in[1];
    const float* W   = (const float*)d_in[2];
    const float* a   = (const float*)d_in[3];
    const float* Wp  = (const float*)d_in[4];
    const float* bp  = (const float*)d_in[5];
    // d_in[6] is k (=20), compiled in.

    prep_kernel<<<NROWS / 4, 256>>>(x, pos, W, a);
    gat_kernel<<<NROWS, 256>>>(Wp, bp, (float*)d_out);
}

// round 12
// speedup vs baseline: 2.6835x; 2.5898x over previous
#include <cuda_runtime.h>
#include <math.h>
#include <float.h>

#define BATCH 2
#define NPTS  4096
#define FDIM  64
#define KNN   20
#define NROWS (BATCH*NPTS)
#define NSEL  (KNN + 1)          // 21: top-21, rank 0 (self) dropped
#define SELCAP 288

// Scratch (static __device__ arrays -- no allocation)
__device__ float  g_Wh[NROWS*FDIM];
__device__ float  g_f1[NROWS];
__device__ float  g_f2[NROWS];
__device__ float4 g_pos4[NROWS];

// ---------------------------------------------------------------------------
// Kernel 1: Wh = x@W ; f1 = Wh@a[:64] ; f2 = Wh@a[64:] ; pos4 = (x,y,z,|p|^2)
// 16 rows per block (512 blocks) -> W loaded into smem 4x less often.
// ---------------------------------------------------------------------------
__global__ void __launch_bounds__(256) prep_kernel(
        const float* __restrict__ x,
        const float* __restrict__ pos,
        const float* __restrict__ W,
        const float* __restrict__ a)
{
    __shared__ float WsT[FDIM*68];     // WsT[f*68 + k2] = W[k2*64 + f]
    __shared__ float xs[4][FDIM];
    __shared__ float red1[8];
    __shared__ float red2[8];

    int tid = threadIdx.x;
    for (int i = tid; i < FDIM*FDIM; i += 256)
        WsT[(i & 63)*68 + (i >> 6)] = W[i];

    int r    = tid >> 6;           // local row 0..3
    int f    = tid & 63;           // feature
    int warp = tid >> 5;
    float a1 = a[f];
    float a2 = a[FDIM + f];

    for (int it = 0; it < 4; it++) {
        int row = blockIdx.x * 16 + it * 4 + r;
        xs[r][f] = x[row*FDIM + f];
        __syncthreads();

        float acc = 0.f;
        #pragma unroll
        for (int k4 = 0; k4 < 16; k4++) {
            float4 xv = *(const float4*)&xs[r][k4*4];
            float4 wv = *(const float4*)&WsT[f*68 + k4*4];
            acc += xv.x*wv.x; acc += xv.y*wv.y;
            acc += xv.z*wv.z; acc += xv.w*wv.w;
        }
        g_Wh[row*FDIM + f] = acc;

        float c1 = acc * a1;
        float c2 = acc * a2;
        #pragma unroll
        for (int off = 16; off; off >>= 1) {
            c1 += __shfl_down_sync(0xffffffffu, c1, off);
            c2 += __shfl_down_sync(0xffffffffu, c2, off);
        }
        if ((tid & 31) == 0) { red1[warp] = c1; red2[warp] = c2; }
        __syncthreads();
        if (f == 0) {
            g_f1[row] = red1[2*r] + red1[2*r + 1];
            g_f2[row] = red2[2*r] + red2[2*r + 1];
        }
    }

    if (tid < 16) {
        int rw = blockIdx.x * 16 + tid;
        float px = pos[rw*3 + 0], py = pos[rw*3 + 1], pz = pos[rw*3 + 2];
        g_pos4[rw] = make_float4(px, py, pz, px*px + py*py + pz*pz);
    }
}

// Order-preserving f32 -> u32 map (min over keys == min over floats)
__device__ __forceinline__ unsigned mono32(float v) {
    unsigned u = __float_as_uint(v);
    return u ^ ((unsigned)((int)u >> 31) | 0x80000000u);
}

// min over 16 u32 keys, returns (key<<4)|slot  (explicit tree, no dyn index)
__device__ __forceinline__ unsigned long long min16(const unsigned* k) {
    unsigned long long t0  = (((unsigned long long)k[0])  << 4) | 0;
    unsigned long long t1  = (((unsigned long long)k[1])  << 4) | 1;
    unsigned long long t2  = (((unsigned long long)k[2])  << 4) | 2;
    unsigned long long t3  = (((unsigned long long)k[3])  << 4) | 3;
    unsigned long long t4  = (((unsigned long long)k[4])  << 4) | 4;
    unsigned long long t5  = (((unsigned long long)k[5])  << 4) | 5;
    unsigned long long t6  = (((unsigned long long)k[6])  << 4) | 6;
    unsigned long long t7  = (((unsigned long long)k[7])  << 4) | 7;
    unsigned long long t8  = (((unsigned long long)k[8])  << 4) | 8;
    unsigned long long t9  = (((unsigned long long)k[9])  << 4) | 9;
    unsigned long long t10 = (((unsigned long long)k[10]) << 4) | 10;
    unsigned long long t11 = (((unsigned long long)k[11]) << 4) | 11;
    unsigned long long t12 = (((unsigned long long)k[12]) << 4) | 12;
    unsigned long long t13 = (((unsigned long long)k[13]) << 4) | 13;
    unsigned long long t14 = (((unsigned long long)k[14]) << 4) | 14;
    unsigned long long t15 = (((unsigned long long)k[15]) << 4) | 15;
    unsigned long long a0 = t0  < t1  ? t0  : t1;
    unsigned long long a1 = t2  < t3  ? t2  : t3;
    unsigned long long a2 = t4  < t5  ? t4  : t5;
    unsigned long long a3 = t6  < t7  ? t6  : t7;
    unsigned long long a4 = t8  < t9  ? t8  : t9;
    unsigned long long a5 = t10 < t11 ? t10 : t11;
    unsigned long long a6 = t12 < t13 ? t12 : t13;
    unsigned long long a7 = t14 < t15 ? t14 : t15;
    unsigned long long b0 = a0 < a1 ? a0 : a1;
    unsigned long long b1 = a2 < a3 ? a2 : a3;
    unsigned long long b2 = a4 < a5 ? a4 : a5;
    unsigned long long b3 = a6 < a7 ? a6 : a7;
    unsigned long long c0 = b0 < b1 ? b0 : b1;
    unsigned long long c1 = b2 < b3 ? b2 : b3;
    return c0 < c1 ? c0 : c1;
}

// min over 8 u64 values (explicit tree)
__device__ __forceinline__ unsigned long long min8u64(const unsigned long long* v) {
    unsigned long long a0 = v[0] < v[1] ? v[0] : v[1];
    unsigned long long a1 = v[2] < v[3] ? v[2] : v[3];
    unsigned long long a2 = v[4] < v[5] ? v[4] : v[5];
    unsigned long long a3 = v[6] < v[7] ? v[6] : v[7];
    unsigned long long b0 = a0 < a1 ? a0 : a1;
    unsigned long long b1 = a2 < a3 ? a2 : a3;
    return b0 < b1 ? b0 : b1;
}

// ---------------------------------------------------------------------------
// Kernel 2: fused KNN(21) + edge softmax + aggregation + pos MLP.
// Filter-then-select: T = 21st smallest of the 256 per-thread local minima
// (a subset => T >= true K21). Filter keys <= T (tiny list), exact
// rank-select on it reproduces jax.lax.top_k (value, then lowest index).
// 5 block barriers total.
// ---------------------------------------------------------------------------
__global__ void __launch_bounds__(256) gat_kernel(
        const float* __restrict__ Wp,
        const float* __restrict__ bp,
        float* __restrict__ out)
{
    __shared__ unsigned long long lmin[256];   // per-thread local min: key<<12 | m
    __shared__ unsigned long long sel[SELCAP]; // filtered candidates
    __shared__ unsigned T_s, sel_cnt;
    __shared__ int   nbr[NSEL];                // winners in exact top_k order
    __shared__ float attn[KNN];

    int tid  = threadIdx.x;
    int lane = tid & 31;
    int warp = tid >> 5;

    int q = blockIdx.x;          // flattened b*N + n
    int b = q >> 12;             // N = 4096
    const float4* posb = g_pos4 + (b << 12);
    float4 qp = g_pos4[q];

    if (tid == 0) sel_cnt = 0;

    // ---- Phase 1: monotonic d2 keys, 16 per thread (m = s*256 + tid) ----
    unsigned key[16];
    #pragma unroll
    for (int s = 0; s < 16; s++) {
        float4 p = posb[s*256 + tid];
        float dot = qp.x*p.x + qp.y*p.y + qp.z*p.z;
        float d2  = (qp.w + p.w) - 2.0f*dot;     // identical to passing kernels
        key[s] = mono32(d2);
    }
    {
        unsigned long long lk = min16(key);      // (key<<4)|slot
        unsigned m_local = ((unsigned)(lk & 15u) << 8) | (unsigned)tid;
        lmin[tid] = ((lk >> 4) << 12) | m_local; // key<<12 | m
    }
    __syncthreads();                             // (1)

    // ---- Phase 2: warp 0 extracts 21st smallest of the 256 local minima ----
    if (warp == 0) {
        unsigned long long v[8];
        #pragma unroll
        for (int i = 0; i < 8; i++)
            v[i] = (lmin[lane + 32*i] << 3) | (unsigned)i;   // (key<<15)|(m<<3)|i
        unsigned long long mv = min8u64(v);

        unsigned Tl = 0;
        for (int r = 0; r < NSEL; r++) {
            unsigned k32 = (unsigned)(mv >> 15);
            unsigned wk  = __reduce_min_sync(0xffffffffu, k32);
            unsigned m12 = (unsigned)(mv >> 3) & 0xFFFu;
            unsigned am  = (k32 == wk) ? m12 : 0xFFFFu;
            unsigned wm  = __reduce_min_sync(0xffffffffu, am);
            if (k32 == wk && m12 == wm) {        // unique owner lane
                int slot = (int)(mv & 7u);
                #pragma unroll
                for (int i = 0; i < 8; i++) if (i == slot) v[i] = ~0ULL;
                mv = min8u64(v);
            }
            Tl = wk;                             // after last round: 21st value
        }
        if (lane == 0) T_s = Tl;
    }
    __syncthreads();                             // (2)

    // ---- Phase 3: filter keys <= T, ballot-compact into sel[] ----
    unsigned T = T_s;
    #pragma unroll
    for (int s = 0; s < 16; s++) {
        bool f = (key[s] <= T);
        unsigned bal = __ballot_sync(0xffffffffu, f);
        if (bal) {
            int leader = __ffs(bal) - 1;
            unsigned base = 0;
            if (lane == leader) base = atomicAdd(&sel_cnt, (unsigned)__popc(bal));
            base = __shfl_sync(0xffffffffu, base, leader);
            if (f) {
                unsigned pos = base + (unsigned)__popc(bal & ((1u << lane) - 1u));
                if (pos < SELCAP)
                    sel[pos] = (((unsigned long long)key[s]) << 12)
                             | (unsigned)(s*256 + tid);
            }
        }
    }
    __syncthreads();                             // (3)

    // ---- Phase 4: exact rank-select (keys unique: (d2,index) lex order) ----
    unsigned L = min(sel_cnt, (unsigned)SELCAP);
    if (tid < (int)L) {
        unsigned long long myk = sel[tid];
        int rank = 0;
        for (unsigned j = 0; j < L; j++) rank += (sel[j] < myk);
        if (rank < NSEL) nbr[rank] = (int)(myk & 0xFFFu);
    }
    __syncthreads();                             // (4)

    // ---- Phase 5: edge scores + softmax over the 20 neighbors (warp 0) ----
    if (warp == 0) {
        float e = -FLT_MAX;
        if (lane >= 1 && lane < NSEL) {
            int m = nbr[lane];
            e = g_f1[q] + g_f2[(b << 12) + m];
            e = (e > 0.f) ? e : 0.2f * e;        // leaky relu
        }
        float mx = e;
        #pragma unroll
        for (int off = 16; off; off >>= 1)
            mx = fmaxf(mx, __shfl_xor_sync(0xffffffffu, mx, off));
        float p = (lane >= 1 && lane < NSEL) ? expf(e - mx) : 0.f;
        float sm = p;
        #pragma unroll
        for (int off = 16; off; off >>= 1)
            sm += __shfl_xor_sync(0xffffffffu, sm, off);
        if (lane >= 1 && lane < NSEL) attn[lane - 1] = p / sm;
    }
    __syncthreads();                             // (5)

    // ---- Phase 6: h = attn @ Wh[nbr] + relu(pos@Wp + bp); elu ----
    if (tid < FDIM) {
        const float* whb = g_Wh + ((size_t)(b << 12)) * FDIM;
        float acc = 0.f;
        #pragma unroll
        for (int j = 0; j < KNN; j++)
            acc += attn[j] * whb[nbr[j + 1] * FDIM + tid];
        float pf = qp.x*Wp[tid] + qp.y*Wp[FDIM + tid] + qp.z*Wp[2*FDIM + tid] + bp[tid];
        pf = fmaxf(pf, 0.f);
        float h = acc + pf;
        out[(size_t)q * FDIM + tid] = (h > 0.f) ? h : expm1f(h);
    }
}

// ---------------------------------------------------------------------------
extern "C" void kernel_launch(void* const* d_in, const int* in_sizes, int n_in,
                              void* d_out, int out_size)
{
    const float* x   = (const float*)d_in[0];
    const float* pos = (const float*)d_in[1];
    const float* W   = (const float*)d_in[2];
    const float* a   = (const float*)d_in[3];
    const float* Wp  = (const float*)d_in[4];
    const float* bp  = (const float*)d_in[5];
    // d_in[6] is k (=20), compiled in.

    prep_kernel<<<NROWS / 16, 256>>>(x, pos, W, a);
    gat_kernel<<<NROWS, 256>>>(Wp, bp, (float*)d_out);
}

// round 17
// speedup vs baseline: 3.5588x; 1.3262x over previous
#include <cuda_runtime.h>
#include <math.h>
#include <float.h>

#define BATCH 2
#define NPTS  4096
#define FDIM  64
#define KNN   20
#define NROWS (BATCH*NPTS)
#define NSEL  (KNN + 1)          // 21: top-21, rank 0 (self) dropped
#define SELCAP 288

// Scratch (static __device__ arrays -- no allocation)
__device__ float  g_Wh[NROWS*FDIM];
__device__ float  g_f1[NROWS];
__device__ float  g_f2[NROWS];
__device__ float4 g_pos4[NROWS];

// ---------------------------------------------------------------------------
// Kernel 1: Wh = x@W ; f1 = Wh@a[:64] ; f2 = Wh@a[64:] ; pos4 = (x,y,z,|p|^2)
// 16 rows per block (512 blocks).
// ---------------------------------------------------------------------------
__global__ void __launch_bounds__(256) prep_kernel(
        const float* __restrict__ x,
        const float* __restrict__ pos,
        const float* __restrict__ W,
        const float* __restrict__ a)
{
    __shared__ float WsT[FDIM*68];     // WsT[f*68 + k2] = W[k2*64 + f]
    __shared__ float xs[4][FDIM];
    __shared__ float red1[8];
    __shared__ float red2[8];

    int tid = threadIdx.x;
    for (int i = tid; i < FDIM*FDIM; i += 256)
        WsT[(i & 63)*68 + (i >> 6)] = W[i];

    int r    = tid >> 6;           // local row 0..3
    int f    = tid & 63;           // feature
    int warp = tid >> 5;
    float a1 = a[f];
    float a2 = a[FDIM + f];

    for (int it = 0; it < 4; it++) {
        int row = blockIdx.x * 16 + it * 4 + r;
        xs[r][f] = x[row*FDIM + f];
        __syncthreads();

        float acc = 0.f;
        #pragma unroll
        for (int k4 = 0; k4 < 16; k4++) {
            float4 xv = *(const float4*)&xs[r][k4*4];
            float4 wv = *(const float4*)&WsT[f*68 + k4*4];
            acc += xv.x*wv.x; acc += xv.y*wv.y;
            acc += xv.z*wv.z; acc += xv.w*wv.w;
        }
        g_Wh[row*FDIM + f] = acc;

        float c1 = acc * a1;
        float c2 = acc * a2;
        #pragma unroll
        for (int off = 16; off; off >>= 1) {
            c1 += __shfl_down_sync(0xffffffffu, c1, off);
            c2 += __shfl_down_sync(0xffffffffu, c2, off);
        }
        if ((tid & 31) == 0) { red1[warp] = c1; red2[warp] = c2; }
        __syncthreads();
        if (f == 0) {
            g_f1[row] = red1[2*r] + red1[2*r + 1];
            g_f2[row] = red2[2*r] + red2[2*r + 1];
        }
    }

    if (tid < 16) {
        int rw = blockIdx.x * 16 + tid;
        float px = pos[rw*3 + 0], py = pos[rw*3 + 1], pz = pos[rw*3 + 2];
        g_pos4[rw] = make_float4(px, py, pz, px*px + py*py + pz*pz);
    }
}

// Order-preserving f32 -> u32 map (min over keys == min over floats)
__device__ __forceinline__ unsigned mono32(float v) {
    unsigned u = __float_as_uint(v);
    return u ^ ((unsigned)((int)u >> 31) | 0x80000000u);
}

// Fixed-sequence d2 key: identical bits in phase 1 and phase 3.
__device__ __forceinline__ unsigned d2key(float4 qp, float4 p) {
    float dot = __fmaf_rn(qp.z, p.z, __fmaf_rn(qp.y, p.y, __fmul_rn(qp.x, p.x)));
    float d2  = __fmaf_rn(-2.0f, dot, __fadd_rn(qp.w, p.w));
    return mono32(d2);
}

// min over 8 u64 values (explicit tree)
__device__ __forceinline__ unsigned long long min8u64(const unsigned long long* v) {
    unsigned long long a0 = v[0] < v[1] ? v[0] : v[1];
    unsigned long long a1 = v[2] < v[3] ? v[2] : v[3];
    unsigned long long a2 = v[4] < v[5] ? v[4] : v[5];
    unsigned long long a3 = v[6] < v[7] ? v[6] : v[7];
    unsigned long long b0 = a0 < a1 ? a0 : a1;
    unsigned long long b1 = a2 < a3 ? a2 : a3;
    return b0 < b1 ? b0 : b1;
}

// ---------------------------------------------------------------------------
// Kernel 2: fused KNN(21) + edge softmax + aggregation + pos MLP.
// TWO queries per 256-thread block. Filter-then-select per query:
//   T = 21st smallest of the 256 per-thread local minima (>= true K21);
//   filter key <= T (recomputed, bit-identical); exact rank-select on the
//   tiny list reproduces jax.lax.top_k (value, then lowest index).
// Warp 0 / warp 1 run the two tournaments concurrently. 5 barriers / 2 queries.
// ---------------------------------------------------------------------------
__global__ void __launch_bounds__(256, 5) gat_kernel(
        const float* __restrict__ Wp,
        const float* __restrict__ bp,
        float* __restrict__ out)
{
    __shared__ unsigned long long lminA[256], lminB[256]; // key<<12 | m
    __shared__ unsigned long long selA[SELCAP], selB[SELCAP];
    __shared__ unsigned T_s[2];
    __shared__ unsigned cntA, cntB;
    __shared__ int   nbrA[NSEL], nbrB[NSEL];
    __shared__ float attnA[KNN], attnB[KNN];

    int tid  = threadIdx.x;
    int lane = tid & 31;
    int warp = tid >> 5;

    int q0 = blockIdx.x * 2;         // two queries, same batch (NPTS even)
    int q1 = q0 + 1;
    int b  = q0 >> 12;
    const float4* posb = g_pos4 + (b << 12);
    float4 qpA = g_pos4[q0];
    float4 qpB = g_pos4[q1];

    if (tid == 0) { cntA = 0; cntB = 0; }

    // ---- Phase 1: running local min per thread, both queries ----
    unsigned ka = 0xFFFFFFFFu, kb = 0xFFFFFFFFu;
    int sa = 0, sb = 0;
    #pragma unroll
    for (int s = 0; s < 16; s++) {
        float4 p = posb[s*256 + tid];
        unsigned kA = d2key(qpA, p);
        unsigned kB = d2key(qpB, p);
        if (kA < ka) { ka = kA; sa = s; }
        if (kB < kb) { kb = kB; sb = s; }
    }
    lminA[tid] = (((unsigned long long)ka) << 12) | (unsigned)((sa << 8) | tid);
    lminB[tid] = (((unsigned long long)kb) << 12) | (unsigned)((sb << 8) | tid);
    __syncthreads();                             // (1)

    // ---- Phase 2: warps 0/1 extract the 21st smallest local min (exact) ----
    if (warp < 2) {
        const unsigned long long* lm = (warp == 0) ? lminA : lminB;
        unsigned long long v[8];
        #pragma unroll
        for (int i = 0; i < 8; i++)
            v[i] = (lm[lane + 32*i] << 3) | (unsigned)i;  // (key<<15)|(m<<3)|i
        unsigned long long mv = min8u64(v);

        unsigned Tl = 0;
        for (int r = 0; r < NSEL; r++) {
            unsigned k32 = (unsigned)(mv >> 15);
            unsigned wk  = __reduce_min_sync(0xffffffffu, k32);
            unsigned m12 = (unsigned)(mv >> 3) & 0xFFFu;
            unsigned am  = (k32 == wk) ? m12 : 0xFFFFu;
            unsigned wm  = __reduce_min_sync(0xffffffffu, am);
            if (k32 == wk && m12 == wm) {        // unique owner lane
                int slot = (int)(mv & 7u);
                #pragma unroll
                for (int i = 0; i < 8; i++) if (i == slot) v[i] = ~0ULL;
                mv = min8u64(v);
            }
            Tl = wk;                             // after last round: 21st value
        }
        if (lane == 0) T_s[warp] = Tl;
    }
    __syncthreads();                             // (2)

    // ---- Phase 3: filter (recomputed keys) <= T, ballot-compact ----
    {
        unsigned TA = T_s[0], TB = T_s[1];
        #pragma unroll
        for (int s = 0; s < 16; s++) {
            float4 p = posb[s*256 + tid];        // L1 hit (loaded in phase 1)
            unsigned kA = d2key(qpA, p);
            unsigned kB = d2key(qpB, p);
            unsigned m  = (unsigned)(s*256 + tid);

            bool fa = (kA <= TA);
            unsigned balA = __ballot_sync(0xffffffffu, fa);
            if (balA) {
                int leader = __ffs(balA) - 1;
                unsigned base = 0;
                if (lane == leader) base = atomicAdd(&cntA, (unsigned)__popc(balA));
                base = __shfl_sync(0xffffffffu, base, leader);
                if (fa) {
                    unsigned pos = base + (unsigned)__popc(balA & ((1u << lane) - 1u));
                    if (pos < SELCAP)
                        selA[pos] = (((unsigned long long)kA) << 12) | m;
                }
            }
            bool fb = (kB <= TB);
            unsigned balB = __ballot_sync(0xffffffffu, fb);
            if (balB) {
                int leader = __ffs(balB) - 1;
                unsigned base = 0;
                if (lane == leader) base = atomicAdd(&cntB, (unsigned)__popc(balB));
                base = __shfl_sync(0xffffffffu, base, leader);
                if (fb) {
                    unsigned pos = base + (unsigned)__popc(balB & ((1u << lane) - 1u));
                    if (pos < SELCAP)
                        selB[pos] = (((unsigned long long)kB) << 12) | m;
                }
            }
        }
    }
    __syncthreads();                             // (3)

    // ---- Phase 4: exact rank-select, half the block per query ----
    {
        int half = tid >> 7;                     // 0 -> A, 1 -> B
        int t    = tid & 127;
        const unsigned long long* S = half ? selB : selA;
        int* NB = half ? nbrB : nbrA;
        unsigned L = min(half ? cntB : cntA, (unsigned)SELCAP);
        for (unsigned i = t; i < L; i += 128) {
            unsigned long long myk = S[i];
            int rank = 0;
            for (unsigned j = 0; j < L; j++) rank += (S[j] < myk);
            if (rank < NSEL) NB[rank] = (int)(myk & 0xFFFu);
        }
    }
    __syncthreads();                             // (4)

    // ---- Phase 5: softmax over the 20 neighbors (warp 0: A, warp 1: B) ----
    if (warp < 2) {
        int q = (warp == 0) ? q0 : q1;
        const int* NB  = (warp == 0) ? nbrA  : nbrB;
        float*    ATT  = (warp == 0) ? attnA : attnB;
        float e = -FLT_MAX;
        if (lane >= 1 && lane < NSEL) {
            int m = NB[lane];
            e = g_f1[q] + g_f2[(b << 12) + m];
            e = (e > 0.f) ? e : 0.2f * e;        // leaky relu
        }
        float mx = e;
        #pragma unroll
        for (int off = 16; off; off >>= 1)
            mx = fmaxf(mx, __shfl_xor_sync(0xffffffffu, mx, off));
        float p = (lane >= 1 && lane < NSEL) ? expf(e - mx) : 0.f;
        float sm = p;
        #pragma unroll
        for (int off = 16; off; off >>= 1)
            sm += __shfl_xor_sync(0xffffffffu, sm, off);
        if (lane >= 1 && lane < NSEL) ATT[lane - 1] = p / sm;
    }
    __syncthreads();                             // (5)

    // ---- Phase 6: h = attn @ Wh[nbr] + relu(pos@Wp + bp); elu ----
    if (tid < 2*FDIM) {
        int half = tid >> 6;                     // 0 -> A, 1 -> B
        int f    = tid & 63;
        int q    = half ? q1 : q0;
        float4 qp = half ? qpB : qpA;
        const int*   NB  = half ? nbrB  : nbrA;
        const float* ATT = half ? attnB : attnA;
        const float* whb = g_Wh + ((size_t)(b << 12)) * FDIM;
        float acc = 0.f;
        #pragma unroll
        for (int j = 0; j < KNN; j++)
            acc += ATT[j] * whb[NB[j + 1] * FDIM + f];
        float pf = qp.x*Wp[f] + qp.y*Wp[FDIM + f] + qp.z*Wp[2*FDIM + f] + bp[f];
        pf = fmaxf(pf, 0.f);
        float h = acc + pf;
        out[(size_t)q * FDIM + f] = (h > 0.f) ? h : expm1f(h);
    }
}

// ---------------------------------------------------------------------------
extern "C" void kernel_launch(void* const* d_in, const int* in_sizes, int n_in,
                              void* d_out, int out_size)
{
    const float* x   = (const float*)d_in[0];
    const float* pos = (const float*)d_in[1];
    const float* W   = (const float*)d_in[2];
    const float* a   = (const float*)d_in[3];
    const float* Wp  = (const float*)d_in[4];
    const float* bp  = (const float*)d_in[5];
    // d_in[6] is k (=20), compiled in.

    prep_kernel<<<NROWS / 16, 256>>>(x, pos, W, a);
    gat_kernel<<<NROWS / 2, 256>>>(Wp, bp, (float*)d_out);
}